// round 12
// baseline (speedup 1.0000x reference)
#include <cuda_runtime.h>
#include <cstdint>

// ---------------------------------------------------------------------------
// VQ nearest-code quantization + cosine score — 1xTF32 mma.sync + exact refine.
// R12: 128x64 passes, 3 CTAs/SM (6 warps/SMSP), R10's proven scalar-LDS loop.
// ---------------------------------------------------------------------------

namespace {
constexpr int kC    = 256;
constexpr int kNE   = 1024;
constexpr int kCHW  = 256 * 1024;
constexpr int kNTok = 64 * 1024;
constexpr int kZQ   = kNTok * kC;
constexpr int kCOS  = 64 * 32 * 256;
constexpr int kOffCos  = kZQ;
constexpr int kOffIdxG = kZQ + kCOS;
constexpr int kOffIdxZ = kOffIdxG + kNTok;
constexpr int kFlagCap = 2 * kNTok;
constexpr float kMargin = 2e-3f;          // ~10 sigma of tf32(rna) dot error
}

__device__ float g_codeNorm[kNE];
__device__ float g_tokNorm[2 * kNTok];
__device__ int   g_idx[2 * kNTok];
__device__ float g_blimb[1024 * 256];             // tf32-rounded codebook (k-major)
__device__ float g_alimb[2ll * 65536 * 256];      // tf32-rounded tokens, token-major
__device__ int   g_flagCount;
__device__ int   g_flagList[kFlagCap];
__device__ unsigned long long g_refKey[kFlagCap];

// ------------------------------ helpers ------------------------------------
__device__ __forceinline__ uint32_t smem_u32(const void* p) {
    uint32_t a;
    asm("{ .reg .u64 t; cvta.to.shared.u64 t, %1; cvt.u32.u64 %0, t; }"
        : "=r"(a) : "l"(p));
    return a;
}
__device__ __forceinline__ float to_tf32(float x) {
    float r; asm("cvt.rna.tf32.f32 %0, %1;" : "=f"(r) : "f"(x)); return r;
}
__device__ __forceinline__ void cp16(uint32_t dst, const float* src) {
    asm volatile("cp.async.cg.shared.global [%0], [%1], 16;"
                 :: "r"(dst), "l"(src) : "memory");
}
#define CP_COMMIT() asm volatile("cp.async.commit_group;" ::: "memory")
#define CP_WAIT0()  asm volatile("cp.async.wait_group 0;" ::: "memory")

#define MMA(d, a, b0, b1) \
    asm volatile("mma.sync.aligned.m16n8k8.row.col.f32.tf32.tf32.f32 " \
        "{%0,%1,%2,%3}, {%4,%5,%6,%7}, {%8,%9}, {%0,%1,%2,%3};" \
        : "+f"((d)[0]), "+f"((d)[1]), "+f"((d)[2]), "+f"((d)[3]) \
        : "r"((a)[0]), "r"((a)[1]), "r"((a)[2]), "r"((a)[3]), "r"(b0), "r"(b1))

// SMEM: stage s (s=0,1) at s*27648: A [128][36]f @0, B [64][36]f @18432
#define BUF     27648
#define SM_B    18432
#define SM_NORM 55296
#define SM_RV   55552
#define SM_RI   56576
#define SM_RV2  57600
#define SMEM_BYTES 58624

// ---------------------------------------------------------------------------
// #1: codebook prep — one block per code row; exact norm chain by thread 0.
__global__ void prep_cb_kernel(const float* __restrict__ cb) {
    __shared__ float row[256];
    int j = blockIdx.x, tid = threadIdx.x;
    if (j == 0 && tid == 0) g_flagCount = 0;
    row[tid] = cb[j * kC + tid];
    __syncthreads();
    if (tid == 0) {
        float s = 0.f;
        for (int c = 0; c < kC; ++c) s = fmaf(row[c], row[c], s);
        g_codeNorm[j] = s;
    }
    g_blimb[j * kC + tid] = to_tf32(row[tid]);
}

// #2: exact token norms (ascending-c fmaf chain, matches refine).
__global__ void prep_tok_kernel(const float* __restrict__ z,
                                const float* __restrict__ gt) {
    int t = blockIdx.x * blockDim.x + threadIdx.x;
    if (t >= 2 * kNTok) return;
    const float* src = (t < kNTok) ? z : gt;
    int tl = t & (kNTok - 1);
    const float* p = src + (tl >> 10) * kCHW + (tl & 1023);
    float s = 0.f;
    for (int c = 0; c < kC; ++c) { float a = p[c * 1024]; s = fmaf(a, a, s); }
    g_tokNorm[t] = s;
}

// #3: transpose+round z/gt: g_alimb[tensor][tok][k]  (float4 stores)
__global__ void alimb_kernel(const float* __restrict__ z,
                             const float* __restrict__ gt) {
    __shared__ float s[32][33];
    int blk = blockIdx.x;                 // 2 * 64 * 32 * 8
    int tensor = blk >> 14;
    int b   = (blk >> 8) & 63;
    int hwT = (blk >> 3) & 31;
    int cT  = blk & 7;
    const float* src = tensor ? gt : z;
    int tid = threadIdx.x;
#pragma unroll
    for (int u = 0; u < 4; u++) {
        int cl = (tid >> 5) + u * 8, hw = tid & 31;
        s[cl][hw] = src[b * kCHW + (cT * 32 + cl) * 1024 + hwT * 32 + hw];
    }
    __syncthreads();
    int tokl = tid >> 3, c4 = tid & 7;
    float4 hi;
    hi.x = to_tf32(s[c4 * 4 + 0][tokl]);
    hi.y = to_tf32(s[c4 * 4 + 1][tokl]);
    hi.z = to_tf32(s[c4 * 4 + 2][tokl]);
    hi.w = to_tf32(s[c4 * 4 + 3][tokl]);
    size_t base = ((size_t)tensor * 65536 + b * 1024 + hwT * 32 + tokl) * 256
                + cT * 32 + c4 * 4;
    *(float4*)(g_alimb + base) = hi;
}

// ---------------------------------------------------------------------------
__device__ __forceinline__ void issue_copy(uint32_t sb, int tid, int t,
                                           int tensor, int tloc) {
    const int pass = t >> 3, chunk = t & 7;
    const uint32_t dB = sb + (t & 1) * BUF;
#pragma unroll
    for (int u = 0; u < 4; u++) {                       // A: 1024 f4
        int i = tid + u * 256;
        int tok = i >> 3, k4 = i & 7;
        const float* src = g_alimb +
            ((size_t)tensor * 65536 + tloc + tok) * 256 + chunk * 32 + k4 * 4;
        cp16(dB + tok * 144 + k4 * 16, src);
    }
#pragma unroll
    for (int u = 0; u < 2; u++) {                       // B: 512 f4
        int i = tid + u * 256;
        int code = i >> 3, k4 = i & 7;
        const float* src = g_blimb +
            ((size_t)(pass * 64 + code)) * 256 + chunk * 32 + k4 * 4;
        cp16(dB + SM_B + code * 144 + k4 * 16, src);
    }
}

// #4 (ncu slot): GEMM + top-2 argmin; 16 passes of 64 codes, 2-stage pipeline.
__global__ void __launch_bounds__(256, 3)
argmin_mma_kernel() {
    extern __shared__ char smem[];
    const uint32_t sb = smem_u32(smem);
    const int tid = threadIdx.x, lane = tid & 31, w = tid >> 5;
    const int r0 = lane >> 2, cg = lane & 3;
    const int mw = w & 3, nw = w >> 2;                  // nw in 0..1
    const int tensor = blockIdx.x >> 9;
    const int tloc = (blockIdx.x & 511) * 128;

    float sTok[4];
#pragma unroll
    for (int s = 0; s < 4; s++)
        sTok[s] = g_tokNorm[tensor * kNTok + tloc + mw * 32 + (s >> 1) * 16 + (s & 1) * 8 + r0];

    float rowV = 3.4e38f, rowV2 = 3.4e38f; int rowI = 0;
    float acc[2][4][4];

    issue_copy(sb, tid, 0, tensor, tloc); CP_COMMIT();

    for (int t = 0; t < 128; t++) {
        const int pass = t >> 3, chunk = t & 7;
        CP_WAIT0();
        __syncthreads();
        if (t + 1 < 128) { issue_copy(sb, tid, t + 1, tensor, tloc); CP_COMMIT(); }
        if (chunk == 0) {
            if (tid < 64)
                *(float*)(smem + SM_NORM + tid * 4) = g_codeNorm[pass * 64 + tid];
#pragma unroll
            for (int i = 0; i < 2; i++)
#pragma unroll
                for (int j = 0; j < 4; j++)
#pragma unroll
                    for (int q = 0; q < 4; q++) acc[i][j][q] = 0.f;
        }
        const char* bp = smem + (t & 1) * BUF;
#pragma unroll
        for (int ks = 0; ks < 4; ks++) {
            uint32_t aH[2][4];
#pragma unroll
            for (int i = 0; i < 2; i++) {
                const char* ab = bp + (mw * 32 + i * 16 + r0) * 144 + (ks * 8 + cg) * 4;
                aH[i][0] = *(const uint32_t*)ab;
                aH[i][1] = *(const uint32_t*)(ab + 8 * 144);
                aH[i][2] = *(const uint32_t*)(ab + 16);
                aH[i][3] = *(const uint32_t*)(ab + 8 * 144 + 16);
            }
#pragma unroll
            for (int j = 0; j < 4; j++) {
                const char* bb = bp + SM_B + (nw * 32 + j * 8 + r0) * 144 + (ks * 8 + cg) * 4;
                uint32_t bh0 = *(const uint32_t*)bb;
                uint32_t bh1 = *(const uint32_t*)(bb + 16);
                MMA(acc[0][j], aH[0], bh0, bh1);
                MMA(acc[1][j], aH[1], bh0, bh1);
            }
        }
        if (chunk == 7) {
#pragma unroll
            for (int i = 0; i < 2; i++)
#pragma unroll
                for (int p = 0; p < 2; p++) {
                    float v1 = 3.4e38f, v2 = 3.4e38f; int i1 = 0;
#pragma unroll
                    for (int j = 0; j < 4; j++)
#pragma unroll
                        for (int q = 0; q < 2; q++) {
                            int cl = nw * 32 + j * 8 + cg * 2 + q;
                            float n = *(const float*)(smem + SM_NORM + cl * 4);
                            float d = __fadd_rn(__fadd_rn(sTok[i * 2 + p], n),
                                                -__fmul_rn(2.0f, acc[i][j][p * 2 + q]));
                            if (d < v1) { v2 = v1; v1 = d; i1 = cl; }
                            else if (d < v2) v2 = d;
                        }
                    for (int off = 1; off < 4; off <<= 1) {
                        float ov1 = __shfl_xor_sync(0xffffffffu, v1, off);
                        float ov2 = __shfl_xor_sync(0xffffffffu, v2, off);
                        int   oi1 = __shfl_xor_sync(0xffffffffu, i1, off);
                        if (ov1 < v1 || (ov1 == v1 && oi1 < i1)) {
                            v2 = fminf(v1, ov2); v1 = ov1; i1 = oi1;
                        } else {
                            v2 = fminf(v2, ov1);
                        }
                    }
                    if (cg == 0) {
                        int row = mw * 32 + i * 16 + p * 8 + r0;
                        *(float*)(smem + SM_RV  + (nw * 128 + row) * 4) = v1;
                        *(int*)  (smem + SM_RI  + (nw * 128 + row) * 4) = i1;
                        *(float*)(smem + SM_RV2 + (nw * 128 + row) * 4) = v2;
                    }
                }
            __syncthreads();
            if (tid < 128) {
                float a1 = *(float*)(smem + SM_RV + tid * 4);
                int   ai = *(int*)  (smem + SM_RI + tid * 4);
                float a2 = *(float*)(smem + SM_RV2 + tid * 4);
                float b1 = *(float*)(smem + SM_RV + (128 + tid) * 4);
                int   bi = *(int*)  (smem + SM_RI + (128 + tid) * 4);
                float b2 = *(float*)(smem + SM_RV2 + (128 + tid) * 4);
                if (b1 < a1) { a2 = fminf(a1, b2); a1 = b1; ai = bi; }
                else         { a2 = fminf(a2, b1); }
                if (a1 < rowV) { rowV2 = fminf(rowV, a2); rowV = a1; rowI = pass * 64 + ai; }
                else           { rowV2 = fminf(rowV2, a1); }
            }
        }
    }
    if (tid < 128) {
        int t = tensor * kNTok + tloc + tid;
        g_idx[t] = rowI;
        if (rowV2 - rowV < kMargin) {
            int slot = atomicAdd(&g_flagCount, 1);
            if (slot < kFlagCap) {
                g_flagList[slot] = t;
                g_refKey[slot] = 0xFFFFFFFFFFFFFFFFull;
            }
        }
    }
}

// ---------------------------------------------------------------------------
// #5: batched exact re-check; item = (batch of 16 tokens, quarter of codes).
// Merge via atomicMin on (d_bits<<32)|code — order-independent, low-idx tie-break.
__global__ void __launch_bounds__(256)
refine_kernel(const float* __restrict__ z, const float* __restrict__ gt,
              const float* __restrict__ cb) {
    __shared__ float xs[16][260];
    __shared__ float dm[16][257];
    __shared__ float sn[16];
    __shared__ int   st[16];
    __shared__ int   sf[16];
    int nf = g_flagCount; if (nf > kFlagCap) nf = kFlagCap;
    int nItems = ((nf + 15) >> 4) * 4;
    const int tid = threadIdx.x, lane = tid & 31, w = tid >> 5;
    for (int item = blockIdx.x; item < nItems; item += gridDim.x) {
        int b = item >> 2, s = item & 3;
        __syncthreads();
#pragma unroll
        for (int ii = 0; ii < 2; ii++) {
            int i = w * 2 + ii;
            int slot = b * 16 + i;
            int ok = slot < nf;
            int tk = g_flagList[ok ? slot : nf - 1];
            int tensor = tk >> 16, tl = tk & 65535;
            const float* src = (tensor ? gt : z) + (tl >> 10) * kCHW + (tl & 1023);
            for (int k = lane; k < 256; k += 32) xs[i][k] = src[k * 1024];
            if (lane == 0) { st[i] = ok ? tk : -1; sf[i] = slot; sn[i] = g_tokNorm[tk]; }
        }
        __syncthreads();
        const float4* e4 = (const float4*)(cb + (s * 256 + tid) * 256);
        float acc[16];
#pragma unroll
        for (int i = 0; i < 16; i++) acc[i] = 0.f;
        float4 ev = e4[0];
        for (int k4 = 0; k4 < 64; k4++) {
            float4 evn = e4[(k4 + 1) & 63];
#pragma unroll
            for (int i = 0; i < 16; i++) {
                float4 xv = *(const float4*)&xs[i][k4 * 4];
                acc[i] = fmaf(xv.x, ev.x, acc[i]);
                acc[i] = fmaf(xv.y, ev.y, acc[i]);
                acc[i] = fmaf(xv.z, ev.z, acc[i]);
                acc[i] = fmaf(xv.w, ev.w, acc[i]);
            }
            ev = evn;
        }
        float cn = g_codeNorm[s * 256 + tid];
#pragma unroll
        for (int i = 0; i < 16; i++)
            dm[i][tid] = __fadd_rn(__fadd_rn(sn[i], cn),
                                   -__fmul_rn(2.0f, acc[i]));
        __syncthreads();
#pragma unroll
        for (int ii = 0; ii < 2; ii++) {
            int i = w * 2 + ii;
            float v = 3.4e38f; int vi = 0x7fffffff;
            for (int jj = lane; jj < 256; jj += 32) {
                float d = dm[i][jj]; int ci = s * 256 + jj;
                if (d < v || (d == v && ci < vi)) { v = d; vi = ci; }
            }
            for (int off = 16; off > 0; off >>= 1) {
                float ovv = __shfl_xor_sync(0xffffffffu, v, off);
                int   ovi = __shfl_xor_sync(0xffffffffu, vi, off);
                if (ovv < v || (ovv == v && ovi < vi)) { v = ovv; vi = ovi; }
            }
            if (lane == 0 && st[i] >= 0) {
                unsigned long long key =
                    ((unsigned long long)__float_as_uint(v) << 32) | (unsigned)vi;
                atomicMin(&g_refKey[sf[i]], key);
            }
        }
    }
}

// #6: commit refined winners.
__global__ void refine_commit_kernel() {
    int f = blockIdx.x * blockDim.x + threadIdx.x;
    int nf = g_flagCount; if (nf > kFlagCap) nf = kFlagCap;
    if (f < nf)
        g_idx[g_flagList[f]] = (int)(unsigned)(g_refKey[f] & 0xFFFFFFFFull);
}

// ---------------------------------------------------------------------------
__global__ void write_zq_kernel(const float* __restrict__ cb,
                                float* __restrict__ out) {
    int i = blockIdx.x * blockDim.x + threadIdx.x;
    int t = i >> 6, cq = i & 63;
    int idx = g_idx[t];
    ((float4*)out)[i] = ((const float4*)(cb + idx * kC))[cq];
}

__global__ void write_idx_kernel(float* __restrict__ out) {
    int t = blockIdx.x * blockDim.x + threadIdx.x;
    if (t >= kNTok) return;
    out[kOffIdxG + t] = (float)g_idx[kNTok + t];
    out[kOffIdxZ + t] = (float)g_idx[t];
}

__global__ void cosine_kernel(const float* __restrict__ cb,
                              float* __restrict__ out) {
    int bw = blockIdx.x;
    int b = bw >> 5, w = bw & 31;
    int c = threadIdx.x;
    __shared__ int sig[32], siz[32];
    if (threadIdx.x < 32) {
        int h = threadIdx.x;
        int t = b * 1024 + h * 32 + w;
        sig[h] = g_idx[kNTok + t];
        siz[h] = g_idx[t];
    }
    __syncthreads();
    float num = 0.f, ng = 0.f, nz = 0.f;
    for (int h = 0; h < 32; ++h) {
        float g = cb[sig[h] * kC + c];
        float q = cb[siz[h] * kC + c];
        num = fmaf(g, q, num);
        ng  = fmaf(g, g, ng);
        nz  = fmaf(q, q, nz);
    }
    float den = fmaxf(sqrtf(ng), 1e-8f) * fmaxf(sqrtf(nz), 1e-8f);
    out[kOffCos + bw * kC + c] = num / den;
}

// ---------------------------------------------------------------------------
extern "C" void kernel_launch(void* const* d_in, const int* in_sizes, int n_in,
                              void* d_out, int out_size) {
    const float* z  = (const float*)d_in[0];
    const float* gt = (const float*)d_in[1];
    const float* cb = (const float*)d_in[2];
    float* out = (float*)d_out;
    (void)in_sizes; (void)n_in; (void)out_size;

    cudaFuncSetAttribute(argmin_mma_kernel,
                         cudaFuncAttributeMaxDynamicSharedMemorySize, SMEM_BYTES);

    prep_cb_kernel<<<1024, 256>>>(cb);                           // launch 1
    prep_tok_kernel<<<512, 256>>>(z, gt);                        // launch 2
    alimb_kernel<<<32768, 256>>>(z, gt);                         // launch 3
    argmin_mma_kernel<<<1024, 256, SMEM_BYTES>>>();              // launch 4 (ncu)
    refine_kernel<<<2048, 256>>>(z, gt, cb);                     // launch 5
    refine_commit_kernel<<<kFlagCap / 256, 256>>>();             // launch 6
    write_zq_kernel<<<(kZQ / 4) / 256, 256>>>(cb, out);          // launch 7
    write_idx_kernel<<<(kNTok + 255) / 256, 256>>>(out);         // launch 8
    cosine_kernel<<<64 * 32, 256>>>(cb, out);                    // launch 9
}

// round 14
// speedup vs baseline: 1.5344x; 1.5344x over previous
#include <cuda_runtime.h>
#include <cuda_fp16.h>
#include <cstdint>

// ---------------------------------------------------------------------------
// VQ nearest-code quantization + cosine score — fp16 mma.sync + exact refine.
// R14: R13 plan with the alimb bit-copy compile fix.
// ---------------------------------------------------------------------------

namespace {
constexpr int kC    = 256;
constexpr int kNE   = 1024;
constexpr int kCHW  = 256 * 1024;
constexpr int kNTok = 64 * 1024;
constexpr int kZQ   = kNTok * kC;
constexpr int kCOS  = 64 * 32 * 256;
constexpr int kOffCos  = kZQ;
constexpr int kOffIdxG = kZQ + kCOS;
constexpr int kOffIdxZ = kOffIdxG + kNTok;
constexpr int kFlagCap = 2 * kNTok;
constexpr float kMargin = 2e-3f;          // ~7 sigma of fp16-input fp32-accum dot error
}

__device__ float g_codeNorm[kNE];
__device__ float g_tokNorm[2 * kNTok];
__device__ int   g_idx[2 * kNTok];
__device__ __half g_blimb[1024 * 256];            // fp16 codebook (k-major)
__device__ __half g_alimb[2ll * 65536 * 256];     // fp16 tokens, token-major (64 MiB)
__device__ int   g_flagCount;
__device__ int   g_flagList[kFlagCap];
__device__ unsigned long long g_refKey[kFlagCap];

// ------------------------------ helpers ------------------------------------
__device__ __forceinline__ uint32_t smem_u32(const void* p) {
    uint32_t a;
    asm("{ .reg .u64 t; cvta.to.shared.u64 t, %1; cvt.u32.u64 %0, t; }"
        : "=r"(a) : "l"(p));
    return a;
}
__device__ __forceinline__ void cp16(uint32_t dst, const void* src) {
    asm volatile("cp.async.cg.shared.global [%0], [%1], 16;"
                 :: "r"(dst), "l"(src) : "memory");
}
#define CP_COMMIT() asm volatile("cp.async.commit_group;" ::: "memory")
#define CP_WAIT1()  asm volatile("cp.async.wait_group 1;" ::: "memory")
#define CP_WAIT0()  asm volatile("cp.async.wait_group 0;" ::: "memory")

#define MMA16(d, a, b0, b1) \
    asm volatile("mma.sync.aligned.m16n8k16.row.col.f32.f16.f16.f32 " \
        "{%0,%1,%2,%3}, {%4,%5,%6,%7}, {%8,%9}, {%0,%1,%2,%3};" \
        : "+f"((d)[0]), "+f"((d)[1]), "+f"((d)[2]), "+f"((d)[3]) \
        : "r"((a)[0]), "r"((a)[1]), "r"((a)[2]), "r"((a)[3]), "r"(b0), "r"(b1))

// SMEM: stage s (s=0..2) at s*20480: A [128 rows][80B] @0, B [128 rows][80B] @10240
#define BUF     20480
#define SM_B    10240
#define SM_NORM 61440
#define SM_RV   61952
#define SM_RI   62976
#define SM_RV2  64000
#define SMEM_BYTES 65024

// ---------------------------------------------------------------------------
// #1: codebook prep — one block per code row; exact norm chain by thread 0.
__global__ void prep_cb_kernel(const float* __restrict__ cb) {
    __shared__ float row[256];
    int j = blockIdx.x, tid = threadIdx.x;
    if (j == 0 && tid == 0) g_flagCount = 0;
    row[tid] = cb[j * kC + tid];
    __syncthreads();
    if (tid == 0) {
        float s = 0.f;
        for (int c = 0; c < kC; ++c) s = fmaf(row[c], row[c], s);
        g_codeNorm[j] = s;
    }
    g_blimb[j * kC + tid] = __float2half(row[tid]);
}

// #2: exact token norms (ascending-c fmaf chain, matches refine).
__global__ void prep_tok_kernel(const float* __restrict__ z,
                                const float* __restrict__ gt) {
    int t = blockIdx.x * blockDim.x + threadIdx.x;
    if (t >= 2 * kNTok) return;
    const float* src = (t < kNTok) ? z : gt;
    int tl = t & (kNTok - 1);
    const float* p = src + (tl >> 10) * kCHW + (tl & 1023);
    float s = 0.f;
    for (int c = 0; c < kC; ++c) { float a = p[c * 1024]; s = fmaf(a, a, s); }
    g_tokNorm[t] = s;
}

// #3: transpose+round z/gt: g_alimb[tensor][tok][k]  (8B stores)
__global__ void alimb_kernel(const float* __restrict__ z,
                             const float* __restrict__ gt) {
    __shared__ float s[32][33];
    int blk = blockIdx.x;                 // 2 * 64 * 32 * 8
    int tensor = blk >> 14;
    int b   = (blk >> 8) & 63;
    int hwT = (blk >> 3) & 31;
    int cT  = blk & 7;
    const float* src = tensor ? gt : z;
    int tid = threadIdx.x;
#pragma unroll
    for (int u = 0; u < 4; u++) {
        int cl = (tid >> 5) + u * 8, hw = tid & 31;
        s[cl][hw] = src[b * kCHW + (cT * 32 + cl) * 1024 + hwT * 32 + hw];
    }
    __syncthreads();
    int tokl = tid >> 3, c4 = tid & 7;
    __half2 p0 = __floats2half2_rn(s[c4 * 4 + 0][tokl], s[c4 * 4 + 1][tokl]);
    __half2 p1 = __floats2half2_rn(s[c4 * 4 + 2][tokl], s[c4 * 4 + 3][tokl]);
    size_t base = ((size_t)tensor * 65536 + b * 1024 + hwT * 32 + tokl) * 256
                + cT * 32 + c4 * 4;
    uint2 pk;
    pk.x = *(uint32_t*)&p0;
    pk.y = *(uint32_t*)&p1;
    *(uint2*)(g_alimb + base) = pk;
}

// ---------------------------------------------------------------------------
__device__ __forceinline__ void issue_copy(uint32_t sb, int tid, int t,
                                           int tensor, int tloc) {
    const int pass = t >> 3, chunk = t & 7;
    const uint32_t dB = sb + (t % 3) * BUF;
#pragma unroll
    for (int u = 0; u < 2; u++) {                       // A: 512 x 16B (8 halves)
        int i = tid + u * 256;
        int tok = i >> 2, k8 = i & 3;
        const __half* src = g_alimb +
            ((size_t)tensor * 65536 + tloc + tok) * 256 + chunk * 32 + k8 * 8;
        cp16(dB + tok * 80 + k8 * 16, src);
    }
#pragma unroll
    for (int u = 0; u < 2; u++) {                       // B: 512 x 16B
        int i = tid + u * 256;
        int code = i >> 2, k8 = i & 3;
        const __half* src = g_blimb +
            ((size_t)(pass * 128 + code)) * 256 + chunk * 32 + k8 * 8;
        cp16(dB + SM_B + code * 80 + k8 * 16, src);
    }
}

// #4 (ncu slot): fp16 GEMM + top-2 argmin; 3-stage pipeline (R10 shape).
__global__ void __launch_bounds__(256, 2)
argmin_mma_kernel() {
    extern __shared__ char smem[];
    const uint32_t sb = smem_u32(smem);
    const int tid = threadIdx.x, lane = tid & 31, w = tid >> 5;
    const int r0 = lane >> 2, cg = lane & 3;
    const int mw = w & 3, nw = w >> 2;                  // nw in 0..1
    const int tensor = blockIdx.x >> 9;
    const int tloc = (blockIdx.x & 511) * 128;

    float sTok[4];
#pragma unroll
    for (int s = 0; s < 4; s++)
        sTok[s] = g_tokNorm[tensor * kNTok + tloc + mw * 32 + (s >> 1) * 16 + (s & 1) * 8 + r0];

    float rowV = 3.4e38f, rowV2 = 3.4e38f; int rowI = 0;
    float acc[2][8][4];

    issue_copy(sb, tid, 0, tensor, tloc); CP_COMMIT();
    issue_copy(sb, tid, 1, tensor, tloc); CP_COMMIT();

    for (int t = 0; t < 64; t++) {
        const int pass = t >> 3, chunk = t & 7;
        if (t == 63) CP_WAIT0(); else CP_WAIT1();
        __syncthreads();
        if (t + 2 < 64) { issue_copy(sb, tid, t + 2, tensor, tloc); CP_COMMIT(); }
        if (chunk == 0) {
            if (tid < 128)
                *(float*)(smem + SM_NORM + tid * 4) = g_codeNorm[pass * 128 + tid];
#pragma unroll
            for (int i = 0; i < 2; i++)
#pragma unroll
                for (int j = 0; j < 8; j++)
#pragma unroll
                    for (int q = 0; q < 4; q++) acc[i][j][q] = 0.f;
        }
        const char* bp = smem + (t % 3) * BUF;
#pragma unroll
        for (int h = 0; h < 2; h++) {                   // two k16 steps per 32-chunk
            uint32_t aH[2][4];
#pragma unroll
            for (int i = 0; i < 2; i++) {
                const char* ab = bp + (mw * 32 + i * 16 + r0) * 80 + h * 32 + cg * 4;
                aH[i][0] = *(const uint32_t*)ab;               // row r0,   k 2cg..2cg+1
                aH[i][1] = *(const uint32_t*)(ab + 8 * 80);    // row r0+8
                aH[i][2] = *(const uint32_t*)(ab + 16);        // row r0,   k 2cg+8..9
                aH[i][3] = *(const uint32_t*)(ab + 8 * 80 + 16);
            }
#pragma unroll
            for (int j = 0; j < 8; j++) {
                const char* bb = bp + SM_B + (nw * 64 + j * 8 + r0) * 80 + h * 32 + cg * 4;
                uint32_t bh0 = *(const uint32_t*)bb;
                uint32_t bh1 = *(const uint32_t*)(bb + 16);
                MMA16(acc[0][j], aH[0], bh0, bh1);
                MMA16(acc[1][j], aH[1], bh0, bh1);
            }
        }
        if (chunk == 7) {
#pragma unroll
            for (int i = 0; i < 2; i++)
#pragma unroll
                for (int p = 0; p < 2; p++) {
                    float v1 = 3.4e38f, v2 = 3.4e38f; int i1 = 0;
#pragma unroll
                    for (int j = 0; j < 8; j++)
#pragma unroll
                        for (int q = 0; q < 2; q++) {
                            int cl = nw * 64 + j * 8 + cg * 2 + q;
                            float n = *(const float*)(smem + SM_NORM + cl * 4);
                            float d = __fadd_rn(__fadd_rn(sTok[i * 2 + p], n),
                                                -__fmul_rn(2.0f, acc[i][j][p * 2 + q]));
                            if (d < v1) { v2 = v1; v1 = d; i1 = cl; }
                            else if (d < v2) v2 = d;
                        }
                    for (int off = 1; off < 4; off <<= 1) {
                        float ov1 = __shfl_xor_sync(0xffffffffu, v1, off);
                        float ov2 = __shfl_xor_sync(0xffffffffu, v2, off);
                        int   oi1 = __shfl_xor_sync(0xffffffffu, i1, off);
                        if (ov1 < v1 || (ov1 == v1 && oi1 < i1)) {
                            v2 = fminf(v1, ov2); v1 = ov1; i1 = oi1;
                        } else {
                            v2 = fminf(v2, ov1);
                        }
                    }
                    if (cg == 0) {
                        int row = mw * 32 + i * 16 + p * 8 + r0;
                        *(float*)(smem + SM_RV  + (nw * 128 + row) * 4) = v1;
                        *(int*)  (smem + SM_RI  + (nw * 128 + row) * 4) = i1;
                        *(float*)(smem + SM_RV2 + (nw * 128 + row) * 4) = v2;
                    }
                }
            __syncthreads();
            if (tid < 128) {
                float a1 = *(float*)(smem + SM_RV + tid * 4);
                int   ai = *(int*)  (smem + SM_RI + tid * 4);
                float a2 = *(float*)(smem + SM_RV2 + tid * 4);
                float b1 = *(float*)(smem + SM_RV + (128 + tid) * 4);
                int   bi = *(int*)  (smem + SM_RI + (128 + tid) * 4);
                float b2 = *(float*)(smem + SM_RV2 + (128 + tid) * 4);
                if (b1 < a1) { a2 = fminf(a1, b2); a1 = b1; ai = bi; }
                else         { a2 = fminf(a2, b1); }
                if (a1 < rowV) { rowV2 = fminf(rowV, a2); rowV = a1; rowI = pass * 128 + ai; }
                else           { rowV2 = fminf(rowV2, a1); }
            }
        }
    }
    if (tid < 128) {
        int t = tensor * kNTok + tloc + tid;
        g_idx[t] = rowI;
        if (rowV2 - rowV < kMargin) {
            int slot = atomicAdd(&g_flagCount, 1);
            if (slot < kFlagCap) {
                g_flagList[slot] = t;
                g_refKey[slot] = 0xFFFFFFFFFFFFFFFFull;
            }
        }
    }
}

// ---------------------------------------------------------------------------
// #5: batched exact re-check; item = (batch of 16 tokens, quarter of codes).
// Merge via atomicMin on (d_bits<<32)|code — order-independent, low-idx tie-break.
__global__ void __launch_bounds__(256)
refine_kernel(const float* __restrict__ z, const float* __restrict__ gt,
              const float* __restrict__ cb) {
    __shared__ float xs[16][260];
    __shared__ float dm[16][257];
    __shared__ float sn[16];
    __shared__ int   st[16];
    __shared__ int   sf[16];
    int nf = g_flagCount; if (nf > kFlagCap) nf = kFlagCap;
    int nItems = ((nf + 15) >> 4) * 4;
    const int tid = threadIdx.x, lane = tid & 31, w = tid >> 5;
    for (int item = blockIdx.x; item < nItems; item += gridDim.x) {
        int b = item >> 2, s = item & 3;
        __syncthreads();
#pragma unroll
        for (int ii = 0; ii < 2; ii++) {
            int i = w * 2 + ii;
            int slot = b * 16 + i;
            int ok = slot < nf;
            int tk = g_flagList[ok ? slot : nf - 1];
            int tensor = tk >> 16, tl = tk & 65535;
            const float* src = (tensor ? gt : z) + (tl >> 10) * kCHW + (tl & 1023);
            for (int k = lane; k < 256; k += 32) xs[i][k] = src[k * 1024];
            if (lane == 0) { st[i] = ok ? tk : -1; sf[i] = slot; sn[i] = g_tokNorm[tk]; }
        }
        __syncthreads();
        const float4* e4 = (const float4*)(cb + (s * 256 + tid) * 256);
        float acc[16];
#pragma unroll
        for (int i = 0; i < 16; i++) acc[i] = 0.f;
        float4 ev = e4[0];
        for (int k4 = 0; k4 < 64; k4++) {
            float4 evn = e4[(k4 + 1) & 63];
#pragma unroll
            for (int i = 0; i < 16; i++) {
                float4 xv = *(const float4*)&xs[i][k4 * 4];
                acc[i] = fmaf(xv.x, ev.x, acc[i]);
                acc[i] = fmaf(xv.y, ev.y, acc[i]);
                acc[i] = fmaf(xv.z, ev.z, acc[i]);
                acc[i] = fmaf(xv.w, ev.w, acc[i]);
            }
            ev = evn;
        }
        float cn = g_codeNorm[s * 256 + tid];
#pragma unroll
        for (int i = 0; i < 16; i++)
            dm[i][tid] = __fadd_rn(__fadd_rn(sn[i], cn),
                                   -__fmul_rn(2.0f, acc[i]));
        __syncthreads();
#pragma unroll
        for (int ii = 0; ii < 2; ii++) {
            int i = w * 2 + ii;
            float v = 3.4e38f; int vi = 0x7fffffff;
            for (int jj = lane; jj < 256; jj += 32) {
                float d = dm[i][jj]; int ci = s * 256 + jj;
                if (d < v || (d == v && ci < vi)) { v = d; vi = ci; }
            }
            for (int off = 16; off > 0; off >>= 1) {
                float ovv = __shfl_xor_sync(0xffffffffu, v, off);
                int   ovi = __shfl_xor_sync(0xffffffffu, vi, off);
                if (ovv < v || (ovv == v && ovi < vi)) { v = ovv; vi = ovi; }
            }
            if (lane == 0 && st[i] >= 0) {
                unsigned long long key =
                    ((unsigned long long)__float_as_uint(v) << 32) | (unsigned)vi;
                atomicMin(&g_refKey[sf[i]], key);
            }
        }
    }
}

// #6: commit refined winners.
__global__ void refine_commit_kernel() {
    int f = blockIdx.x * blockDim.x + threadIdx.x;
    int nf = g_flagCount; if (nf > kFlagCap) nf = kFlagCap;
    if (f < nf)
        g_idx[g_flagList[f]] = (int)(unsigned)(g_refKey[f] & 0xFFFFFFFFull);
}

// ---------------------------------------------------------------------------
__global__ void write_zq_kernel(const float* __restrict__ cb,
                                float* __restrict__ out) {
    int i = blockIdx.x * blockDim.x + threadIdx.x;
    int t = i >> 6, cq = i & 63;
    int idx = g_idx[t];
    ((float4*)out)[i] = ((const float4*)(cb + idx * kC))[cq];
}

__global__ void write_idx_kernel(float* __restrict__ out) {
    int t = blockIdx.x * blockDim.x + threadIdx.x;
    if (t >= kNTok) return;
    out[kOffIdxG + t] = (float)g_idx[kNTok + t];
    out[kOffIdxZ + t] = (float)g_idx[t];
}

__global__ void cosine_kernel(const float* __restrict__ cb,
                              float* __restrict__ out) {
    int bw = blockIdx.x;
    int b = bw >> 5, w = bw & 31;
    int c = threadIdx.x;
    __shared__ int sig[32], siz[32];
    if (threadIdx.x < 32) {
        int h = threadIdx.x;
        int t = b * 1024 + h * 32 + w;
        sig[h] = g_idx[kNTok + t];
        siz[h] = g_idx[t];
    }
    __syncthreads();
    float num = 0.f, ng = 0.f, nz = 0.f;
    for (int h = 0; h < 32; ++h) {
        float g = cb[sig[h] * kC + c];
        float q = cb[siz[h] * kC + c];
        num = fmaf(g, q, num);
        ng  = fmaf(g, g, ng);
        nz  = fmaf(q, q, nz);
    }
    float den = fmaxf(sqrtf(ng), 1e-8f) * fmaxf(sqrtf(nz), 1e-8f);
    out[kOffCos + bw * kC + c] = num / den;
}

// ---------------------------------------------------------------------------
extern "C" void kernel_launch(void* const* d_in, const int* in_sizes, int n_in,
                              void* d_out, int out_size) {
    const float* z  = (const float*)d_in[0];
    const float* gt = (const float*)d_in[1];
    const float* cb = (const float*)d_in[2];
    float* out = (float*)d_out;
    (void)in_sizes; (void)n_in; (void)out_size;

    cudaFuncSetAttribute(argmin_mma_kernel,
                         cudaFuncAttributeMaxDynamicSharedMemorySize, SMEM_BYTES);

    prep_cb_kernel<<<1024, 256>>>(cb);                           // launch 1
    prep_tok_kernel<<<512, 256>>>(z, gt);                        // launch 2
    alimb_kernel<<<32768, 256>>>(z, gt);                         // launch 3
    argmin_mma_kernel<<<1024, 256, SMEM_BYTES>>>();              // launch 4 (ncu)
    refine_kernel<<<2048, 256>>>(z, gt, cb);                     // launch 5
    refine_commit_kernel<<<kFlagCap / 256, 256>>>();             // launch 6
    write_zq_kernel<<<(kZQ / 4) / 256, 256>>>(cb, out);          // launch 7
    write_idx_kernel<<<(kNTok + 255) / 256, 256>>>(out);         // launch 8
    cosine_kernel<<<64 * 32, 256>>>(cb, out);                    // launch 9
}

// round 15
// speedup vs baseline: 1.8278x; 1.1913x over previous
#include <cuda_runtime.h>
#include <cuda_fp16.h>
#include <cstdint>

// ---------------------------------------------------------------------------
// VQ nearest-code quantization + cosine score — fp16 mma.sync + exact refine.
// R15: k=64 per iteration (half the syncs), token-norm dropped from coarse
// epilogue (cancels in argmin), prep_tok deleted (refine computes norms).
// ---------------------------------------------------------------------------

namespace {
constexpr int kC    = 256;
constexpr int kNE   = 1024;
constexpr int kCHW  = 256 * 1024;
constexpr int kNTok = 64 * 1024;
constexpr int kZQ   = kNTok * kC;
constexpr int kCOS  = 64 * 32 * 256;
constexpr int kOffCos  = kZQ;
constexpr int kOffIdxG = kZQ + kCOS;
constexpr int kOffIdxZ = kOffIdxG + kNTok;
constexpr int kFlagCap = 2 * kNTok;
constexpr float kMargin = 2e-3f;          // ~7 sigma of fp16-input fp32-accum dot error
}

__device__ float g_codeNorm[kNE];
__device__ int   g_idx[2 * kNTok];
__device__ __half g_blimb[1024 * 256];            // fp16 codebook (k-major)
__device__ __half g_alimb[2ll * 65536 * 256];     // fp16 tokens, token-major (64 MiB)
__device__ int   g_flagCount;
__device__ int   g_flagList[kFlagCap];
__device__ unsigned long long g_refKey[kFlagCap];

// ------------------------------ helpers ------------------------------------
__device__ __forceinline__ uint32_t smem_u32(const void* p) {
    uint32_t a;
    asm("{ .reg .u64 t; cvta.to.shared.u64 t, %1; cvt.u32.u64 %0, t; }"
        : "=r"(a) : "l"(p));
    return a;
}
__device__ __forceinline__ void cp16(uint32_t dst, const void* src) {
    asm volatile("cp.async.cg.shared.global [%0], [%1], 16;"
                 :: "r"(dst), "l"(src) : "memory");
}
#define CP_COMMIT() asm volatile("cp.async.commit_group;" ::: "memory")
#define CP_WAIT1()  asm volatile("cp.async.wait_group 1;" ::: "memory")
#define CP_WAIT0()  asm volatile("cp.async.wait_group 0;" ::: "memory")

#define MMA16(d, a, b0, b1) \
    asm volatile("mma.sync.aligned.m16n8k16.row.col.f32.f16.f16.f32 " \
        "{%0,%1,%2,%3}, {%4,%5,%6,%7}, {%8,%9}, {%0,%1,%2,%3};" \
        : "+f"((d)[0]), "+f"((d)[1]), "+f"((d)[2]), "+f"((d)[3]) \
        : "r"((a)[0]), "r"((a)[1]), "r"((a)[2]), "r"((a)[3]), "r"(b0), "r"(b1))

// SMEM: stage s (s=0..2) at s*36864: A [128 rows][144B] @0, B [128 rows][144B] @18432
#define BUF     36864
#define SM_B    18432
#define SM_NORM 110592
#define SM_RV   111104
#define SM_RI   112128
#define SM_RV2  113152
#define SMEM_BYTES 114176

// ---------------------------------------------------------------------------
// #1: codebook prep — one block per code row; exact norm chain by thread 0.
__global__ void prep_cb_kernel(const float* __restrict__ cb) {
    __shared__ float row[256];
    int j = blockIdx.x, tid = threadIdx.x;
    if (j == 0 && tid == 0) g_flagCount = 0;
    row[tid] = cb[j * kC + tid];
    __syncthreads();
    if (tid == 0) {
        float s = 0.f;
        for (int c = 0; c < kC; ++c) s = fmaf(row[c], row[c], s);
        g_codeNorm[j] = s;
    }
    g_blimb[j * kC + tid] = __float2half(row[tid]);
}

// #2/#3: transpose+round one tensor: g_alimb[tensor][tok][k]  (8B stores)
__global__ void alimb_kernel(const float* __restrict__ src0, int tensor) {
    __shared__ float s[32][33];
    int blk = blockIdx.x;                 // 64 * 32 * 8
    int b   = (blk >> 8) & 63;
    int hwT = (blk >> 3) & 31;
    int cT  = blk & 7;
    int tid = threadIdx.x;
#pragma unroll
    for (int u = 0; u < 4; u++) {
        int cl = (tid >> 5) + u * 8, hw = tid & 31;
        s[cl][hw] = src0[b * kCHW + (cT * 32 + cl) * 1024 + hwT * 32 + hw];
    }
    __syncthreads();
    int tokl = tid >> 3, c4 = tid & 7;
    __half2 p0 = __floats2half2_rn(s[c4 * 4 + 0][tokl], s[c4 * 4 + 1][tokl]);
    __half2 p1 = __floats2half2_rn(s[c4 * 4 + 2][tokl], s[c4 * 4 + 3][tokl]);
    size_t base = ((size_t)tensor * 65536 + b * 1024 + hwT * 32 + tokl) * 256
                + cT * 32 + c4 * 4;
    uint2 pk;
    pk.x = *(uint32_t*)&p0;
    pk.y = *(uint32_t*)&p1;
    *(uint2*)(g_alimb + base) = pk;
}

// ---------------------------------------------------------------------------
// copy one k64 slab (chunk = t&3) of A (128 toks) + B (128 codes of pass t>>2)
__device__ __forceinline__ void issue_copy(uint32_t sb, int tid, int t,
                                           int tensor, int tloc) {
    const int pass = t >> 2, chunk = t & 3;
    const uint32_t dB = sb + (t % 3) * BUF;
#pragma unroll
    for (int u = 0; u < 4; u++) {                       // A: 1024 x 16B
        int i = tid + u * 256;
        int tok = i >> 3, k8 = i & 7;
        const __half* src = g_alimb +
            ((size_t)tensor * 65536 + tloc + tok) * 256 + chunk * 64 + k8 * 8;
        cp16(dB + tok * 144 + k8 * 16, src);
    }
#pragma unroll
    for (int u = 0; u < 4; u++) {                       // B: 1024 x 16B
        int i = tid + u * 256;
        int code = i >> 3, k8 = i & 7;
        const __half* src = g_blimb +
            ((size_t)(pass * 128 + code)) * 256 + chunk * 64 + k8 * 8;
        cp16(dB + SM_B + code * 144 + k8 * 16, src);
    }
}

// #4 (ncu slot): fp16 GEMM + top-2 argmin; 32 iters of k=64, 3-stage pipeline.
__global__ void __launch_bounds__(256, 2)
argmin_mma_kernel() {
    extern __shared__ char smem[];
    const uint32_t sb = smem_u32(smem);
    const int tid = threadIdx.x, lane = tid & 31, w = tid >> 5;
    const int r0 = lane >> 2, cg = lane & 3;
    const int mw = w & 3, nw = w >> 2;                  // nw in 0..1
    const int tensor = blockIdx.x >> 9;
    const int tloc = (blockIdx.x & 511) * 128;

    float rowV = 3.4e38f, rowV2 = 3.4e38f; int rowI = 0;
    float acc[2][8][4];

    issue_copy(sb, tid, 0, tensor, tloc); CP_COMMIT();
    issue_copy(sb, tid, 1, tensor, tloc); CP_COMMIT();

    for (int t = 0; t < 32; t++) {
        const int pass = t >> 2, chunk = t & 3;
        if (t == 31) CP_WAIT0(); else CP_WAIT1();
        __syncthreads();
        if (t + 2 < 32) { issue_copy(sb, tid, t + 2, tensor, tloc); CP_COMMIT(); }
        if (chunk == 0) {
            if (tid < 128)
                *(float*)(smem + SM_NORM + tid * 4) = g_codeNorm[pass * 128 + tid];
#pragma unroll
            for (int i = 0; i < 2; i++)
#pragma unroll
                for (int j = 0; j < 8; j++)
#pragma unroll
                    for (int q = 0; q < 4; q++) acc[i][j][q] = 0.f;
        }
        const char* bp = smem + (t % 3) * BUF;
#pragma unroll
        for (int h = 0; h < 4; h++) {                   // four k16 steps per k64 slab
            uint32_t aH[2][4];
#pragma unroll
            for (int i = 0; i < 2; i++) {
                const char* ab = bp + (mw * 32 + i * 16 + r0) * 144 + h * 32 + cg * 4;
                aH[i][0] = *(const uint32_t*)ab;
                aH[i][1] = *(const uint32_t*)(ab + 8 * 144);
                aH[i][2] = *(const uint32_t*)(ab + 16);
                aH[i][3] = *(const uint32_t*)(ab + 8 * 144 + 16);
            }
#pragma unroll
            for (int j = 0; j < 8; j++) {
                const char* bb = bp + SM_B + (nw * 64 + j * 8 + r0) * 144 + h * 32 + cg * 4;
                uint32_t bh0 = *(const uint32_t*)bb;
                uint32_t bh1 = *(const uint32_t*)(bb + 16);
                MMA16(acc[0][j], aH[0], bh0, bh1);
                MMA16(acc[1][j], aH[1], bh0, bh1);
            }
        }
        if (chunk == 3) {
            // top-2 epilogue on d' = n - 2*acc (token norm cancels in argmin)
#pragma unroll
            for (int i = 0; i < 2; i++)
#pragma unroll
                for (int p = 0; p < 2; p++) {
                    float v1 = 3.4e38f, v2 = 3.4e38f; int i1 = 0;
#pragma unroll
                    for (int j = 0; j < 8; j++)
#pragma unroll
                        for (int q = 0; q < 2; q++) {
                            int cl = nw * 64 + j * 8 + cg * 2 + q;
                            float n = *(const float*)(smem + SM_NORM + cl * 4);
                            float d = __fadd_rn(n, -__fmul_rn(2.0f, acc[i][j][p * 2 + q]));
                            if (d < v1) { v2 = v1; v1 = d; i1 = cl; }
                            else if (d < v2) v2 = d;
                        }
                    for (int off = 1; off < 4; off <<= 1) {
                        float ov1 = __shfl_xor_sync(0xffffffffu, v1, off);
                        float ov2 = __shfl_xor_sync(0xffffffffu, v2, off);
                        int   oi1 = __shfl_xor_sync(0xffffffffu, i1, off);
                        if (ov1 < v1 || (ov1 == v1 && oi1 < i1)) {
                            v2 = fminf(v1, ov2); v1 = ov1; i1 = oi1;
                        } else {
                            v2 = fminf(v2, ov1);
                        }
                    }
                    if (cg == 0) {
                        int row = mw * 32 + i * 16 + p * 8 + r0;
                        *(float*)(smem + SM_RV  + (nw * 128 + row) * 4) = v1;
                        *(int*)  (smem + SM_RI  + (nw * 128 + row) * 4) = i1;
                        *(float*)(smem + SM_RV2 + (nw * 128 + row) * 4) = v2;
                    }
                }
            __syncthreads();
            if (tid < 128) {
                float a1 = *(float*)(smem + SM_RV + tid * 4);
                int   ai = *(int*)  (smem + SM_RI + tid * 4);
                float a2 = *(float*)(smem + SM_RV2 + tid * 4);
                float b1 = *(float*)(smem + SM_RV + (128 + tid) * 4);
                int   bi = *(int*)  (smem + SM_RI + (128 + tid) * 4);
                float b2 = *(float*)(smem + SM_RV2 + (128 + tid) * 4);
                if (b1 < a1) { a2 = fminf(a1, b2); a1 = b1; ai = bi; }
                else         { a2 = fminf(a2, b1); }
                if (a1 < rowV) { rowV2 = fminf(rowV, a2); rowV = a1; rowI = pass * 128 + ai; }
                else           { rowV2 = fminf(rowV2, a1); }
            }
        }
    }
    if (tid < 128) {
        int t = tensor * kNTok + tloc + tid;
        g_idx[t] = rowI;
        if (rowV2 - rowV < kMargin) {
            int slot = atomicAdd(&g_flagCount, 1);
            if (slot < kFlagCap) {
                g_flagList[slot] = t;
                g_refKey[slot] = 0xFFFFFFFFFFFFFFFFull;
            }
        }
    }
}

// ---------------------------------------------------------------------------
// #5: batched exact re-check; item = (batch of 16 tokens, quarter of codes).
// Token norms computed in-kernel with the exact ascending-k fmaf chain.
// Merge via atomicMin on (d_bits<<32)|code — order-independent, low-idx tie-break.
__global__ void __launch_bounds__(256)
refine_kernel(const float* __restrict__ z, const float* __restrict__ gt,
              const float* __restrict__ cb) {
    __shared__ float xs[16][260];
    __shared__ float dm[16][257];
    __shared__ float sn[16];
    __shared__ int   st[16];
    __shared__ int   sf[16];
    int nf = g_flagCount; if (nf > kFlagCap) nf = kFlagCap;
    int nItems = ((nf + 15) >> 4) * 4;
    const int tid = threadIdx.x, lane = tid & 31, w = tid >> 5;
    for (int item = blockIdx.x; item < nItems; item += gridDim.x) {
        int b = item >> 2, s = item & 3;
        __syncthreads();
#pragma unroll
        for (int ii = 0; ii < 2; ii++) {
            int i = w * 2 + ii;
            int slot = b * 16 + i;
            int ok = slot < nf;
            int tk = g_flagList[ok ? slot : nf - 1];
            int tensor = tk >> 16, tl = tk & 65535;
            const float* src = (tensor ? gt : z) + (tl >> 10) * kCHW + (tl & 1023);
            for (int k = lane; k < 256; k += 32) xs[i][k] = src[k * 1024];
            if (lane == 0) { st[i] = ok ? tk : -1; sf[i] = slot; }
        }
        __syncwarp();
        if (lane < 2) {          // exact token norm, ascending-k chain
            int i = w * 2 + lane;
            float sv = 0.f;
            for (int k = 0; k < 256; ++k) sv = fmaf(xs[i][k], xs[i][k], sv);
            sn[i] = sv;
        }
        __syncthreads();
        const float4* e4 = (const float4*)(cb + (s * 256 + tid) * 256);
        float acc[16];
#pragma unroll
        for (int i = 0; i < 16; i++) acc[i] = 0.f;
        float4 ev = e4[0];
        for (int k4 = 0; k4 < 64; k4++) {
            float4 evn = e4[(k4 + 1) & 63];
#pragma unroll
            for (int i = 0; i < 16; i++) {
                float4 xv = *(const float4*)&xs[i][k4 * 4];
                acc[i] = fmaf(xv.x, ev.x, acc[i]);
                acc[i] = fmaf(xv.y, ev.y, acc[i]);
                acc[i] = fmaf(xv.z, ev.z, acc[i]);
                acc[i] = fmaf(xv.w, ev.w, acc[i]);
            }
            ev = evn;
        }
        float cn = g_codeNorm[s * 256 + tid];
#pragma unroll
        for (int i = 0; i < 16; i++)
            dm[i][tid] = __fadd_rn(__fadd_rn(sn[i], cn),
                                   -__fmul_rn(2.0f, acc[i]));
        __syncthreads();
#pragma unroll
        for (int ii = 0; ii < 2; ii++) {
            int i = w * 2 + ii;
            float v = 3.4e38f; int vi = 0x7fffffff;
            for (int jj = lane; jj < 256; jj += 32) {
                float d = dm[i][jj]; int ci = s * 256 + jj;
                if (d < v || (d == v && ci < vi)) { v = d; vi = ci; }
            }
            for (int off = 16; off > 0; off >>= 1) {
                float ovv = __shfl_xor_sync(0xffffffffu, v, off);
                int   ovi = __shfl_xor_sync(0xffffffffu, vi, off);
                if (ovv < v || (ovv == v && ovi < vi)) { v = ovv; vi = ovi; }
            }
            if (lane == 0 && st[i] >= 0) {
                unsigned long long key =
                    ((unsigned long long)__float_as_uint(v) << 32) | (unsigned)vi;
                atomicMin(&g_refKey[sf[i]], key);
            }
        }
    }
}

// #6: commit refined winners.
__global__ void refine_commit_kernel() {
    int f = blockIdx.x * blockDim.x + threadIdx.x;
    int nf = g_flagCount; if (nf > kFlagCap) nf = kFlagCap;
    if (f < nf)
        g_idx[g_flagList[f]] = (int)(unsigned)(g_refKey[f] & 0xFFFFFFFFull);
}

// ---------------------------------------------------------------------------
__global__ void write_zq_kernel(const float* __restrict__ cb,
                                float* __restrict__ out) {
    int i = blockIdx.x * blockDim.x + threadIdx.x;
    int t = i >> 6, cq = i & 63;
    int idx = g_idx[t];
    ((float4*)out)[i] = ((const float4*)(cb + idx * kC))[cq];
}

__global__ void write_idx_kernel(float* __restrict__ out) {
    int t = blockIdx.x * blockDim.x + threadIdx.x;
    if (t >= kNTok) return;
    out[kOffIdxG + t] = (float)g_idx[kNTok + t];
    out[kOffIdxZ + t] = (float)g_idx[t];
}

__global__ void cosine_kernel(const float* __restrict__ cb,
                              float* __restrict__ out) {
    int bw = blockIdx.x;
    int b = bw >> 5, w = bw & 31;
    int c = threadIdx.x;
    __shared__ int sig[32], siz[32];
    if (threadIdx.x < 32) {
        int h = threadIdx.x;
        int t = b * 1024 + h * 32 + w;
        sig[h] = g_idx[kNTok + t];
        siz[h] = g_idx[t];
    }
    __syncthreads();
    float num = 0.f, ng = 0.f, nz = 0.f;
    for (int h = 0; h < 32; ++h) {
        float g = cb[sig[h] * kC + c];
        float q = cb[siz[h] * kC + c];
        num = fmaf(g, q, num);
        ng  = fmaf(g, g, ng);
        nz  = fmaf(q, q, nz);
    }
    float den = fmaxf(sqrtf(ng), 1e-8f) * fmaxf(sqrtf(nz), 1e-8f);
    out[kOffCos + bw * kC + c] = num / den;
}

// ---------------------------------------------------------------------------
extern "C" void kernel_launch(void* const* d_in, const int* in_sizes, int n_in,
                              void* d_out, int out_size) {
    const float* z  = (const float*)d_in[0];
    const float* gt = (const float*)d_in[1];
    const float* cb = (const float*)d_in[2];
    float* out = (float*)d_out;
    (void)in_sizes; (void)n_in; (void)out_size;

    cudaFuncSetAttribute(argmin_mma_kernel,
                         cudaFuncAttributeMaxDynamicSharedMemorySize, SMEM_BYTES);

    prep_cb_kernel<<<1024, 256>>>(cb);                           // launch 1
    alimb_kernel<<<16384, 256>>>(z, 0);                          // launch 2
    alimb_kernel<<<16384, 256>>>(gt, 1);                         // launch 3
    argmin_mma_kernel<<<1024, 256, SMEM_BYTES>>>();              // launch 4 (ncu)
    refine_kernel<<<2048, 256>>>(z, gt, cb);                     // launch 5
    refine_commit_kernel<<<kFlagCap / 256, 256>>>();             // launch 6
    write_zq_kernel<<<(kZQ / 4) / 256, 256>>>(cb, out);          // launch 7
    write_idx_kernel<<<(kNTok + 255) / 256, 256>>>(out);         // launch 8
    cosine_kernel<<<64 * 32, 256>>>(cb, out);                    // launch 9
}

// round 16
// speedup vs baseline: 2.0007x; 1.0946x over previous
#include <cuda_runtime.h>
#include <cuda_fp16.h>
#include <cstdint>

// ---------------------------------------------------------------------------
// VQ nearest-code quantization + cosine score — fp16 mma.sync + exact refine.
// R16: A slice smem-resident (loaded once), double-buffered B slabs only.
// ---------------------------------------------------------------------------

namespace {
constexpr int kC    = 256;
constexpr int kNE   = 1024;
constexpr int kCHW  = 256 * 1024;
constexpr int kNTok = 64 * 1024;
constexpr int kZQ   = kNTok * kC;
constexpr int kCOS  = 64 * 32 * 256;
constexpr int kOffCos  = kZQ;
constexpr int kOffIdxG = kZQ + kCOS;
constexpr int kOffIdxZ = kOffIdxG + kNTok;
constexpr int kFlagCap = 2 * kNTok;
constexpr float kMargin = 2e-3f;          // ~7 sigma of fp16-input fp32-accum dot error
}

__device__ float g_codeNorm[kNE];
__device__ int   g_idx[2 * kNTok];
__device__ __half g_blimb[1024 * 256];            // fp16 codebook (k-major)
__device__ __half g_alimb[2ll * 65536 * 256];     // fp16 tokens, token-major (64 MiB)
__device__ int   g_flagCount;
__device__ int   g_flagList[kFlagCap];
__device__ unsigned long long g_refKey[kFlagCap];

// ------------------------------ helpers ------------------------------------
__device__ __forceinline__ uint32_t smem_u32(const void* p) {
    uint32_t a;
    asm("{ .reg .u64 t; cvta.to.shared.u64 t, %1; cvt.u32.u64 %0, t; }"
        : "=r"(a) : "l"(p));
    return a;
}
__device__ __forceinline__ void cp16(uint32_t dst, const void* src) {
    asm volatile("cp.async.cg.shared.global [%0], [%1], 16;"
                 :: "r"(dst), "l"(src) : "memory");
}
#define CP_COMMIT() asm volatile("cp.async.commit_group;" ::: "memory")
#define CP_WAIT0()  asm volatile("cp.async.wait_group 0;" ::: "memory")

#define MMA16(d, a, b0, b1) \
    asm volatile("mma.sync.aligned.m16n8k16.row.col.f32.f16.f16.f32 " \
        "{%0,%1,%2,%3}, {%4,%5,%6,%7}, {%8,%9}, {%0,%1,%2,%3};" \
        : "+f"((d)[0]), "+f"((d)[1]), "+f"((d)[2]), "+f"((d)[3]) \
        : "r"((a)[0]), "r"((a)[1]), "r"((a)[2]), "r"((a)[3]), "r"(b0), "r"(b1))

// SMEM: A resident [128 rows][528B] @0 (67584 B; bank-perm (4*r0+cg)%32)
//       B stage s (s=0,1) @ 67584 + s*18432  ([128 rows][144B])
#define SM_A_STR 528
#define SM_B0   67584
#define SM_BSTR 18432
#define SM_NORM 104448
#define SM_RV   104960
#define SM_RI   105984
#define SM_RV2  107008
#define SMEM_BYTES 108032

// ---------------------------------------------------------------------------
// #1: codebook prep — one block per code row; exact norm chain by thread 0.
__global__ void prep_cb_kernel(const float* __restrict__ cb) {
    __shared__ float row[256];
    int j = blockIdx.x, tid = threadIdx.x;
    if (j == 0 && tid == 0) g_flagCount = 0;
    row[tid] = cb[j * kC + tid];
    __syncthreads();
    if (tid == 0) {
        float s = 0.f;
        for (int c = 0; c < kC; ++c) s = fmaf(row[c], row[c], s);
        g_codeNorm[j] = s;
    }
    g_blimb[j * kC + tid] = __float2half(row[tid]);
}

// #2/#3: transpose+round one tensor: g_alimb[tensor][tok][k]  (8B stores)
__global__ void alimb_kernel(const float* __restrict__ src0, int tensor) {
    __shared__ float s[32][33];
    int blk = blockIdx.x;                 // 64 * 32 * 8
    int b   = (blk >> 8) & 63;
    int hwT = (blk >> 3) & 31;
    int cT  = blk & 7;
    int tid = threadIdx.x;
#pragma unroll
    for (int u = 0; u < 4; u++) {
        int cl = (tid >> 5) + u * 8, hw = tid & 31;
        s[cl][hw] = src0[b * kCHW + (cT * 32 + cl) * 1024 + hwT * 32 + hw];
    }
    __syncthreads();
    int tokl = tid >> 3, c4 = tid & 7;
    __half2 p0 = __floats2half2_rn(s[c4 * 4 + 0][tokl], s[c4 * 4 + 1][tokl]);
    __half2 p1 = __floats2half2_rn(s[c4 * 4 + 2][tokl], s[c4 * 4 + 3][tokl]);
    size_t base = ((size_t)tensor * 65536 + b * 1024 + hwT * 32 + tokl) * 256
                + cT * 32 + c4 * 4;
    uint2 pk;
    pk.x = *(uint32_t*)&p0;
    pk.y = *(uint32_t*)&p1;
    *(uint2*)(g_alimb + base) = pk;
}

// ---------------------------------------------------------------------------
// A: full 128x256 slice, once (16 cp16 per thread).
__device__ __forceinline__ void issue_copy_A(uint32_t sb, int tid,
                                             int tensor, int tloc) {
#pragma unroll
    for (int u = 0; u < 16; u++) {
        int i = tid + u * 256;
        int tok = i >> 5, k16 = i & 31;
        const __half* src = g_alimb +
            ((size_t)tensor * 65536 + tloc + tok) * 256 + k16 * 8;
        cp16(sb + tok * SM_A_STR + k16 * 16, src);
    }
}
// B: one k64 slab (pass = t>>2, chunk = t&3) of 128 codes.
__device__ __forceinline__ void issue_copy_B(uint32_t sb, int tid, int t) {
    const int pass = t >> 2, chunk = t & 3;
    const uint32_t dB = sb + SM_B0 + (t & 1) * SM_BSTR;
#pragma unroll
    for (int u = 0; u < 4; u++) {
        int i = tid + u * 256;
        int code = i >> 3, k8 = i & 7;
        const __half* src = g_blimb +
            ((size_t)(pass * 128 + code)) * 256 + chunk * 64 + k8 * 8;
        cp16(dB + code * 144 + k8 * 16, src);
    }
}

// #4 (ncu slot): fp16 GEMM + top-2 argmin; A resident, 2-stage B pipeline.
__global__ void __launch_bounds__(256, 2)
argmin_mma_kernel() {
    extern __shared__ char smem[];
    const uint32_t sb = smem_u32(smem);
    const int tid = threadIdx.x, lane = tid & 31, w = tid >> 5;
    const int r0 = lane >> 2, cg = lane & 3;
    const int mw = w & 3, nw = w >> 2;                  // nw in 0..1
    const int tensor = blockIdx.x >> 9;
    const int tloc = (blockIdx.x & 511) * 128;

    float rowV = 3.4e38f, rowV2 = 3.4e38f; int rowI = 0;
    float acc[2][8][4];

    issue_copy_A(sb, tid, tensor, tloc);
    issue_copy_B(sb, tid, 0);
    CP_COMMIT();

    for (int t = 0; t < 32; t++) {
        const int pass = t >> 2, chunk = t & 3;
        CP_WAIT0();                       // slab t (and A at t=0) arrived
        __syncthreads();                  // visibility + buffer (t+1)&1 free
        if (t + 1 < 32) { issue_copy_B(sb, tid, t + 1); CP_COMMIT(); }
        if (chunk == 0) {
            if (tid < 128)
                *(float*)(smem + SM_NORM + tid * 4) = g_codeNorm[pass * 128 + tid];
#pragma unroll
            for (int i = 0; i < 2; i++)
#pragma unroll
                for (int j = 0; j < 8; j++)
#pragma unroll
                    for (int q = 0; q < 4; q++) acc[i][j][q] = 0.f;
        }
        const char* bpB = smem + SM_B0 + (t & 1) * SM_BSTR;
#pragma unroll
        for (int h = 0; h < 4; h++) {                   // four k16 steps per k64 slab
            uint32_t aH[2][4];
#pragma unroll
            for (int i = 0; i < 2; i++) {
                const char* ab = smem + (mw * 32 + i * 16 + r0) * SM_A_STR
                               + chunk * 128 + h * 32 + cg * 4;
                aH[i][0] = *(const uint32_t*)ab;
                aH[i][1] = *(const uint32_t*)(ab + 8 * SM_A_STR);
                aH[i][2] = *(const uint32_t*)(ab + 16);
                aH[i][3] = *(const uint32_t*)(ab + 8 * SM_A_STR + 16);
            }
#pragma unroll
            for (int j = 0; j < 8; j++) {
                const char* bb = bpB + (nw * 64 + j * 8 + r0) * 144 + h * 32 + cg * 4;
                uint32_t bh0 = *(const uint32_t*)bb;
                uint32_t bh1 = *(const uint32_t*)(bb + 16);
                MMA16(acc[0][j], aH[0], bh0, bh1);
                MMA16(acc[1][j], aH[1], bh0, bh1);
            }
        }
        if (chunk == 3) {
            // top-2 epilogue on d' = n - 2*acc (token norm cancels in argmin)
#pragma unroll
            for (int i = 0; i < 2; i++)
#pragma unroll
                for (int p = 0; p < 2; p++) {
                    float v1 = 3.4e38f, v2 = 3.4e38f; int i1 = 0;
#pragma unroll
                    for (int j = 0; j < 8; j++)
#pragma unroll
                        for (int q = 0; q < 2; q++) {
                            int cl = nw * 64 + j * 8 + cg * 2 + q;
                            float n = *(const float*)(smem + SM_NORM + cl * 4);
                            float d = __fadd_rn(n, -__fmul_rn(2.0f, acc[i][j][p * 2 + q]));
                            if (d < v1) { v2 = v1; v1 = d; i1 = cl; }
                            else if (d < v2) v2 = d;
                        }
                    for (int off = 1; off < 4; off <<= 1) {
                        float ov1 = __shfl_xor_sync(0xffffffffu, v1, off);
                        float ov2 = __shfl_xor_sync(0xffffffffu, v2, off);
                        int   oi1 = __shfl_xor_sync(0xffffffffu, i1, off);
                        if (ov1 < v1 || (ov1 == v1 && oi1 < i1)) {
                            v2 = fminf(v1, ov2); v1 = ov1; i1 = oi1;
                        } else {
                            v2 = fminf(v2, ov1);
                        }
                    }
                    if (cg == 0) {
                        int row = mw * 32 + i * 16 + p * 8 + r0;
                        *(float*)(smem + SM_RV  + (nw * 128 + row) * 4) = v1;
                        *(int*)  (smem + SM_RI  + (nw * 128 + row) * 4) = i1;
                        *(float*)(smem + SM_RV2 + (nw * 128 + row) * 4) = v2;
                    }
                }
            __syncthreads();
            if (tid < 128) {
                float a1 = *(float*)(smem + SM_RV + tid * 4);
                int   ai = *(int*)  (smem + SM_RI + tid * 4);
                float a2 = *(float*)(smem + SM_RV2 + tid * 4);
                float b1 = *(float*)(smem + SM_RV + (128 + tid) * 4);
                int   bi = *(int*)  (smem + SM_RI + (128 + tid) * 4);
                float b2 = *(float*)(smem + SM_RV2 + (128 + tid) * 4);
                if (b1 < a1) { a2 = fminf(a1, b2); a1 = b1; ai = bi; }
                else         { a2 = fminf(a2, b1); }
                if (a1 < rowV) { rowV2 = fminf(rowV, a2); rowV = a1; rowI = pass * 128 + ai; }
                else           { rowV2 = fminf(rowV2, a1); }
            }
        }
    }
    if (tid < 128) {
        int t = tensor * kNTok + tloc + tid;
        g_idx[t] = rowI;
        if (rowV2 - rowV < kMargin) {
            int slot = atomicAdd(&g_flagCount, 1);
            if (slot < kFlagCap) {
                g_flagList[slot] = t;
                g_refKey[slot] = 0xFFFFFFFFFFFFFFFFull;
            }
        }
    }
}

// ---------------------------------------------------------------------------
// #5: batched exact re-check; item = (batch of 16 tokens, quarter of codes).
// Token norms computed in-kernel with the exact ascending-k fmaf chain.
// Merge via atomicMin on (d_bits<<32)|code — order-independent, low-idx tie-break.
__global__ void __launch_bounds__(256)
refine_kernel(const float* __restrict__ z, const float* __restrict__ gt,
              const float* __restrict__ cb) {
    __shared__ float xs[16][260];
    __shared__ float dm[16][257];
    __shared__ float sn[16];
    __shared__ int   st[16];
    __shared__ int   sf[16];
    int nf = g_flagCount; if (nf > kFlagCap) nf = kFlagCap;
    int nItems = ((nf + 15) >> 4) * 4;
    const int tid = threadIdx.x, lane = tid & 31, w = tid >> 5;
    for (int item = blockIdx.x; item < nItems; item += gridDim.x) {
        int b = item >> 2, s = item & 3;
        __syncthreads();
#pragma unroll
        for (int ii = 0; ii < 2; ii++) {
            int i = w * 2 + ii;
            int slot = b * 16 + i;
            int ok = slot < nf;
            int tk = g_flagList[ok ? slot : nf - 1];
            int tensor = tk >> 16, tl = tk & 65535;
            const float* src = (tensor ? gt : z) + (tl >> 10) * kCHW + (tl & 1023);
            for (int k = lane; k < 256; k += 32) xs[i][k] = src[k * 1024];
            if (lane == 0) { st[i] = ok ? tk : -1; sf[i] = slot; }
        }
        __syncwarp();
        if (lane < 2) {          // exact token norm, ascending-k chain
            int i = w * 2 + lane;
            float sv = 0.f;
            for (int k = 0; k < 256; ++k) sv = fmaf(xs[i][k], xs[i][k], sv);
            sn[i] = sv;
        }
        __syncthreads();
        const float4* e4 = (const float4*)(cb + (s * 256 + tid) * 256);
        float acc[16];
#pragma unroll
        for (int i = 0; i < 16; i++) acc[i] = 0.f;
        float4 ev = e4[0];
        for (int k4 = 0; k4 < 64; k4++) {
            float4 evn = e4[(k4 + 1) & 63];
#pragma unroll
            for (int i = 0; i < 16; i++) {
                float4 xv = *(const float4*)&xs[i][k4 * 4];
                acc[i] = fmaf(xv.x, ev.x, acc[i]);
                acc[i] = fmaf(xv.y, ev.y, acc[i]);
                acc[i] = fmaf(xv.z, ev.z, acc[i]);
                acc[i] = fmaf(xv.w, ev.w, acc[i]);
            }
            ev = evn;
        }
        float cn = g_codeNorm[s * 256 + tid];
#pragma unroll
        for (int i = 0; i < 16; i++)
            dm[i][tid] = __fadd_rn(__fadd_rn(sn[i], cn),
                                   -__fmul_rn(2.0f, acc[i]));
        __syncthreads();
#pragma unroll
        for (int ii = 0; ii < 2; ii++) {
            int i = w * 2 + ii;
            float v = 3.4e38f; int vi = 0x7fffffff;
            for (int jj = lane; jj < 256; jj += 32) {
                float d = dm[i][jj]; int ci = s * 256 + jj;
                if (d < v || (d == v && ci < vi)) { v = d; vi = ci; }
            }
            for (int off = 16; off > 0; off >>= 1) {
                float ovv = __shfl_xor_sync(0xffffffffu, v, off);
                int   ovi = __shfl_xor_sync(0xffffffffu, vi, off);
                if (ovv < v || (ovv == v && ovi < vi)) { v = ovv; vi = ovi; }
            }
            if (lane == 0 && st[i] >= 0) {
                unsigned long long key =
                    ((unsigned long long)__float_as_uint(v) << 32) | (unsigned)vi;
                atomicMin(&g_refKey[sf[i]], key);
            }
        }
    }
}

// #6: commit refined winners.
__global__ void refine_commit_kernel() {
    int f = blockIdx.x * blockDim.x + threadIdx.x;
    int nf = g_flagCount; if (nf > kFlagCap) nf = kFlagCap;
    if (f < nf)
        g_idx[g_flagList[f]] = (int)(unsigned)(g_refKey[f] & 0xFFFFFFFFull);
}

// ---------------------------------------------------------------------------
__global__ void write_zq_kernel(const float* __restrict__ cb,
                                float* __restrict__ out) {
    int i = blockIdx.x * blockDim.x + threadIdx.x;
    int t = i >> 6, cq = i & 63;
    int idx = g_idx[t];
    ((float4*)out)[i] = ((const float4*)(cb + idx * kC))[cq];
}

__global__ void write_idx_kernel(float* __restrict__ out) {
    int t = blockIdx.x * blockDim.x + threadIdx.x;
    if (t >= kNTok) return;
    out[kOffIdxG + t] = (float)g_idx[kNTok + t];
    out[kOffIdxZ + t] = (float)g_idx[t];
}

__global__ void cosine_kernel(const float* __restrict__ cb,
                              float* __restrict__ out) {
    int bw = blockIdx.x;
    int b = bw >> 5, w = bw & 31;
    int c = threadIdx.x;
    __shared__ int sig[32], siz[32];
    if (threadIdx.x < 32) {
        int h = threadIdx.x;
        int t = b * 1024 + h * 32 + w;
        sig[h] = g_idx[kNTok + t];
        siz[h] = g_idx[t];
    }
    __syncthreads();
    float num = 0.f, ng = 0.f, nz = 0.f;
    for (int h = 0; h < 32; ++h) {
        float g = cb[sig[h] * kC + c];
        float q = cb[siz[h] * kC + c];
        num = fmaf(g, q, num);
        ng  = fmaf(g, g, ng);
        nz  = fmaf(q, q, nz);
    }
    float den = fmaxf(sqrtf(ng), 1e-8f) * fmaxf(sqrtf(nz), 1e-8f);
    out[kOffCos + bw * kC + c] = num / den;
}

// ---------------------------------------------------------------------------
extern "C" void kernel_launch(void* const* d_in, const int* in_sizes, int n_in,
                              void* d_out, int out_size) {
    const float* z  = (const float*)d_in[0];
    const float* gt = (const float*)d_in[1];
    const float* cb = (const float*)d_in[2];
    float* out = (float*)d_out;
    (void)in_sizes; (void)n_in; (void)out_size;

    cudaFuncSetAttribute(argmin_mma_kernel,
                         cudaFuncAttributeMaxDynamicSharedMemorySize, SMEM_BYTES);

    prep_cb_kernel<<<1024, 256>>>(cb);                           // launch 1
    alimb_kernel<<<16384, 256>>>(z, 0);                          // launch 2
    alimb_kernel<<<16384, 256>>>(gt, 1);                         // launch 3
    argmin_mma_kernel<<<1024, 256, SMEM_BYTES>>>();              // launch 4 (ncu)
    refine_kernel<<<2048, 256>>>(z, gt, cb);                     // launch 5
    refine_commit_kernel<<<kFlagCap / 256, 256>>>();             // launch 6
    write_zq_kernel<<<(kZQ / 4) / 256, 256>>>(cb, out);          // launch 7
    write_idx_kernel<<<(kNTok + 255) / 256, 256>>>(out);         // launch 8
    cosine_kernel<<<64 * 32, 256>>>(cb, out);                    // launch 9
}

// round 17
// speedup vs baseline: 2.0078x; 1.0036x over previous
#include <cuda_runtime.h>
#include <cuda_fp16.h>
#include <cstdint>

// ---------------------------------------------------------------------------
// VQ nearest-code quantization + cosine score — fp16 mma.sync + exact refine.
// R17: incremental cp.async addressing; prep and output kernels fused.
// ---------------------------------------------------------------------------

namespace {
constexpr int kC    = 256;
constexpr int kNE   = 1024;
constexpr int kCHW  = 256 * 1024;
constexpr int kNTok = 64 * 1024;
constexpr int kZQ   = kNTok * kC;
constexpr int kCOS  = 64 * 32 * 256;
constexpr int kOffCos  = kZQ;
constexpr int kOffIdxG = kZQ + kCOS;
constexpr int kOffIdxZ = kOffIdxG + kNTok;
constexpr int kFlagCap = 2 * kNTok;
constexpr float kMargin = 2e-3f;          // ~7 sigma of fp16-input fp32-accum dot error
}

__device__ float g_codeNorm[kNE];
__device__ int   g_idx[2 * kNTok];
__device__ __half g_blimb[1024 * 256];            // fp16 codebook (k-major)
__device__ __half g_alimb[2ll * 65536 * 256];     // fp16 tokens, token-major (64 MiB)
__device__ int   g_flagCount;
__device__ int   g_flagList[kFlagCap];
__device__ unsigned long long g_refKey[kFlagCap];

// ------------------------------ helpers ------------------------------------
__device__ __forceinline__ uint32_t smem_u32(const void* p) {
    uint32_t a;
    asm("{ .reg .u64 t; cvta.to.shared.u64 t, %1; cvt.u32.u64 %0, t; }"
        : "=r"(a) : "l"(p));
    return a;
}
__device__ __forceinline__ void cp16(uint32_t dst, const void* src) {
    asm volatile("cp.async.cg.shared.global [%0], [%1], 16;"
                 :: "r"(dst), "l"(src) : "memory");
}
#define CP_COMMIT() asm volatile("cp.async.commit_group;" ::: "memory")
#define CP_WAIT0()  asm volatile("cp.async.wait_group 0;" ::: "memory")

#define MMA16(d, a, b0, b1) \
    asm volatile("mma.sync.aligned.m16n8k16.row.col.f32.f16.f16.f32 " \
        "{%0,%1,%2,%3}, {%4,%5,%6,%7}, {%8,%9}, {%0,%1,%2,%3};" \
        : "+f"((d)[0]), "+f"((d)[1]), "+f"((d)[2]), "+f"((d)[3]) \
        : "r"((a)[0]), "r"((a)[1]), "r"((a)[2]), "r"((a)[3]), "r"(b0), "r"(b1))

// SMEM: A resident [128 rows][528B] @0 (67584 B)
//       B stage s (s=0,1) @ 67584 + s*18432  ([128 rows][144B])
#define SM_A_STR 528
#define SM_B0   67584
#define SM_BSTR 18432
#define SM_NORM 104448
#define SM_RV   104960
#define SM_RI   105984
#define SM_RV2  107008
#define SMEM_BYTES 108032

// ---------------------------------------------------------------------------
// #1: fused prep — codebook norms/rounding + token transpose/rounding.
__global__ void prep_all_kernel(const float* __restrict__ cb,
                                const float* __restrict__ z,
                                const float* __restrict__ gt) {
    int bid = blockIdx.x, tid = threadIdx.x;
    if (bid < 1024) {
        __shared__ float row[256];
        if (bid == 0 && tid == 0) g_flagCount = 0;
        row[tid] = cb[bid * kC + tid];
        __syncthreads();
        if (tid == 0) {
            float s = 0.f;
            for (int c = 0; c < kC; ++c) s = fmaf(row[c], row[c], s);
            g_codeNorm[bid] = s;
        }
        g_blimb[bid * kC + tid] = __float2half(row[tid]);
        return;
    }
    __shared__ float s[32][33];
    int idx = bid - 1024;                 // 0 .. 32767
    int tensor = idx >> 14;
    int blk = idx & 16383;
    int b   = (blk >> 8) & 63;
    int hwT = (blk >> 3) & 31;
    int cT  = blk & 7;
    const float* src = tensor ? gt : z;
#pragma unroll
    for (int u = 0; u < 4; u++) {
        int cl = (tid >> 5) + u * 8, hw = tid & 31;
        s[cl][hw] = src[b * kCHW + (cT * 32 + cl) * 1024 + hwT * 32 + hw];
    }
    __syncthreads();
    int tokl = tid >> 3, c4 = tid & 7;
    __half2 p0 = __floats2half2_rn(s[c4 * 4 + 0][tokl], s[c4 * 4 + 1][tokl]);
    __half2 p1 = __floats2half2_rn(s[c4 * 4 + 2][tokl], s[c4 * 4 + 3][tokl]);
    size_t base = ((size_t)tensor * 65536 + b * 1024 + hwT * 32 + tokl) * 256
                + cT * 32 + c4 * 4;
    uint2 pk;
    pk.x = *(uint32_t*)&p0;
    pk.y = *(uint32_t*)&p1;
    *(uint2*)(g_alimb + base) = pk;
}

// ---------------------------------------------------------------------------
// #2: fp16 GEMM + top-2 argmin; A resident, 2-stage B pipeline,
// incremental copy addressing.
__global__ void __launch_bounds__(256, 2)
argmin_mma_kernel() {
    extern __shared__ char smem[];
    const uint32_t sb = smem_u32(smem);
    const int tid = threadIdx.x, lane = tid & 31, w = tid >> 5;
    const int r0 = lane >> 2, cg = lane & 3;
    const int mw = w & 3, nw = w >> 2;                  // nw in 0..1
    const int tensor = blockIdx.x >> 9;
    const int tloc = (blockIdx.x & 511) * 128;

    // per-thread copy bases (B): src in halves from g_blimb, dst in bytes
    const __half* bSrc[4];
    uint32_t bDst[4];
#pragma unroll
    for (int u = 0; u < 4; u++) {
        int i = tid + u * 256;
        int code = i >> 3, k8 = i & 7;
        bSrc[u] = g_blimb + code * 256 + k8 * 8;
        bDst[u] = sb + SM_B0 + code * 144 + k8 * 16;
    }

    float rowV = 3.4e38f, rowV2 = 3.4e38f; int rowI = 0;
    float acc[2][8][4];

    // A: full slice once
#pragma unroll
    for (int u = 0; u < 16; u++) {
        int i = tid + u * 256;
        int tok = i >> 5, k16 = i & 31;
        const __half* src = g_alimb +
            ((size_t)tensor * 65536 + tloc + tok) * 256 + k16 * 8;
        cp16(sb + tok * SM_A_STR + k16 * 16, src);
    }
    // B slab 0
#pragma unroll
    for (int u = 0; u < 4; u++) cp16(bDst[u], bSrc[u]);
    CP_COMMIT();

    uint32_t nextOff = 64;                // off(t=1), in halves

    for (int t = 0; t < 32; t++) {
        const int pass = t >> 2, chunk = t & 3;
        CP_WAIT0();
        __syncthreads();
        if (t + 1 < 32) {
            const uint32_t dstX = ((t + 1) & 1) * SM_BSTR;
#pragma unroll
            for (int u = 0; u < 4; u++) cp16(bDst[u] + dstX, bSrc[u] + nextOff);
            CP_COMMIT();
            nextOff += (((t + 1) & 3) == 3) ? (32768 - 192) : 64;
        }
        if (chunk == 0) {
            if (tid < 128)
                *(float*)(smem + SM_NORM + tid * 4) = g_codeNorm[pass * 128 + tid];
#pragma unroll
            for (int i = 0; i < 2; i++)
#pragma unroll
                for (int j = 0; j < 8; j++)
#pragma unroll
                    for (int q = 0; q < 4; q++) acc[i][j][q] = 0.f;
        }
        const char* bpB = smem + SM_B0 + (t & 1) * SM_BSTR;
#pragma unroll
        for (int h = 0; h < 4; h++) {                   // four k16 steps per k64 slab
            uint32_t aH[2][4];
#pragma unroll
            for (int i = 0; i < 2; i++) {
                const char* ab = smem + (mw * 32 + i * 16 + r0) * SM_A_STR
                               + chunk * 128 + h * 32 + cg * 4;
                aH[i][0] = *(const uint32_t*)ab;
                aH[i][1] = *(const uint32_t*)(ab + 8 * SM_A_STR);
                aH[i][2] = *(const uint32_t*)(ab + 16);
                aH[i][3] = *(const uint32_t*)(ab + 8 * SM_A_STR + 16);
            }
#pragma unroll
            for (int j = 0; j < 8; j++) {
                const char* bb = bpB + (nw * 64 + j * 8 + r0) * 144 + h * 32 + cg * 4;
                uint32_t bh0 = *(const uint32_t*)bb;
                uint32_t bh1 = *(const uint32_t*)(bb + 16);
                MMA16(acc[0][j], aH[0], bh0, bh1);
                MMA16(acc[1][j], aH[1], bh0, bh1);
            }
        }
        if (chunk == 3) {
            // top-2 epilogue on d' = n - 2*acc (token norm cancels in argmin)
#pragma unroll
            for (int i = 0; i < 2; i++)
#pragma unroll
                for (int p = 0; p < 2; p++) {
                    float v1 = 3.4e38f, v2 = 3.4e38f; int i1 = 0;
#pragma unroll
                    for (int j = 0; j < 8; j++)
#pragma unroll
                        for (int q = 0; q < 2; q++) {
                            int cl = nw * 64 + j * 8 + cg * 2 + q;
                            float n = *(const float*)(smem + SM_NORM + cl * 4);
                            float d = __fadd_rn(n, -__fmul_rn(2.0f, acc[i][j][p * 2 + q]));
                            if (d < v1) { v2 = v1; v1 = d; i1 = cl; }
                            else if (d < v2) v2 = d;
                        }
                    for (int off = 1; off < 4; off <<= 1) {
                        float ov1 = __shfl_xor_sync(0xffffffffu, v1, off);
                        float ov2 = __shfl_xor_sync(0xffffffffu, v2, off);
                        int   oi1 = __shfl_xor_sync(0xffffffffu, i1, off);
                        if (ov1 < v1 || (ov1 == v1 && oi1 < i1)) {
                            v2 = fminf(v1, ov2); v1 = ov1; i1 = oi1;
                        } else {
                            v2 = fminf(v2, ov1);
                        }
                    }
                    if (cg == 0) {
                        int row = mw * 32 + i * 16 + p * 8 + r0;
                        *(float*)(smem + SM_RV  + (nw * 128 + row) * 4) = v1;
                        *(int*)  (smem + SM_RI  + (nw * 128 + row) * 4) = i1;
                        *(float*)(smem + SM_RV2 + (nw * 128 + row) * 4) = v2;
                    }
                }
            __syncthreads();
            if (tid < 128) {
                float a1 = *(float*)(smem + SM_RV + tid * 4);
                int   ai = *(int*)  (smem + SM_RI + tid * 4);
                float a2 = *(float*)(smem + SM_RV2 + tid * 4);
                float b1 = *(float*)(smem + SM_RV + (128 + tid) * 4);
                int   bi = *(int*)  (smem + SM_RI + (128 + tid) * 4);
                float b2 = *(float*)(smem + SM_RV2 + (128 + tid) * 4);
                if (b1 < a1) { a2 = fminf(a1, b2); a1 = b1; ai = bi; }
                else         { a2 = fminf(a2, b1); }
                if (a1 < rowV) { rowV2 = fminf(rowV, a2); rowV = a1; rowI = pass * 128 + ai; }
                else           { rowV2 = fminf(rowV2, a1); }
            }
        }
    }
    if (tid < 128) {
        int t = tensor * kNTok + tloc + tid;
        g_idx[t] = rowI;
        if (rowV2 - rowV < kMargin) {
            int slot = atomicAdd(&g_flagCount, 1);
            if (slot < kFlagCap) {
                g_flagList[slot] = t;
                g_refKey[slot] = 0xFFFFFFFFFFFFFFFFull;
            }
        }
    }
}

// ---------------------------------------------------------------------------
// #3: batched exact re-check; item = (batch of 16 tokens, quarter of codes).
// Token norms computed in-kernel with the exact ascending-k fmaf chain.
// Merge via atomicMin on (d_bits<<32)|code — order-independent, low-idx tie-break.
__global__ void __launch_bounds__(256)
refine_kernel(const float* __restrict__ z, const float* __restrict__ gt,
              const float* __restrict__ cb) {
    __shared__ float xs[16][260];
    __shared__ float dm[16][257];
    __shared__ float sn[16];
    __shared__ int   st[16];
    __shared__ int   sf[16];
    int nf = g_flagCount; if (nf > kFlagCap) nf = kFlagCap;
    int nItems = ((nf + 15) >> 4) * 4;
    const int tid = threadIdx.x, lane = tid & 31, w = tid >> 5;
    for (int item = blockIdx.x; item < nItems; item += gridDim.x) {
        int b = item >> 2, s = item & 3;
        __syncthreads();
#pragma unroll
        for (int ii = 0; ii < 2; ii++) {
            int i = w * 2 + ii;
            int slot = b * 16 + i;
            int ok = slot < nf;
            int tk = g_flagList[ok ? slot : nf - 1];
            int tensor = tk >> 16, tl = tk & 65535;
            const float* src = (tensor ? gt : z) + (tl >> 10) * kCHW + (tl & 1023);
            for (int k = lane; k < 256; k += 32) xs[i][k] = src[k * 1024];
            if (lane == 0) { st[i] = ok ? tk : -1; sf[i] = slot; }
        }
        __syncwarp();
        if (lane < 2) {          // exact token norm, ascending-k chain
            int i = w * 2 + lane;
            float sv = 0.f;
            for (int k = 0; k < 256; ++k) sv = fmaf(xs[i][k], xs[i][k], sv);
            sn[i] = sv;
        }
        __syncthreads();
        const float4* e4 = (const float4*)(cb + (s * 256 + tid) * 256);
        float acc[16];
#pragma unroll
        for (int i = 0; i < 16; i++) acc[i] = 0.f;
        float4 ev = e4[0];
        for (int k4 = 0; k4 < 64; k4++) {
            float4 evn = e4[(k4 + 1) & 63];
#pragma unroll
            for (int i = 0; i < 16; i++) {
                float4 xv = *(const float4*)&xs[i][k4 * 4];
                acc[i] = fmaf(xv.x, ev.x, acc[i]);
                acc[i] = fmaf(xv.y, ev.y, acc[i]);
                acc[i] = fmaf(xv.z, ev.z, acc[i]);
                acc[i] = fmaf(xv.w, ev.w, acc[i]);
            }
            ev = evn;
        }
        float cn = g_codeNorm[s * 256 + tid];
#pragma unroll
        for (int i = 0; i < 16; i++)
            dm[i][tid] = __fadd_rn(__fadd_rn(sn[i], cn),
                                   -__fmul_rn(2.0f, acc[i]));
        __syncthreads();
#pragma unroll
        for (int ii = 0; ii < 2; ii++) {
            int i = w * 2 + ii;
            float v = 3.4e38f; int vi = 0x7fffffff;
            for (int jj = lane; jj < 256; jj += 32) {
                float d = dm[i][jj]; int ci = s * 256 + jj;
                if (d < v || (d == v && ci < vi)) { v = d; vi = ci; }
            }
            for (int off = 16; off > 0; off >>= 1) {
                float ovv = __shfl_xor_sync(0xffffffffu, v, off);
                int   ovi = __shfl_xor_sync(0xffffffffu, vi, off);
                if (ovv < v || (ovv == v && ovi < vi)) { v = ovv; vi = ovi; }
            }
            if (lane == 0 && st[i] >= 0) {
                unsigned long long key =
                    ((unsigned long long)__float_as_uint(v) << 32) | (unsigned)vi;
                atomicMin(&g_refKey[sf[i]], key);
            }
        }
    }
}

// #4: commit refined winners.
__global__ void refine_commit_kernel() {
    int f = blockIdx.x * blockDim.x + threadIdx.x;
    int nf = g_flagCount; if (nf > kFlagCap) nf = kFlagCap;
    if (f < nf)
        g_idx[g_flagList[f]] = (int)(unsigned)(g_refKey[f] & 0xFFFFFFFFull);
}

// ---------------------------------------------------------------------------
// #5: fused outputs — zq gather, idx casts, cosine.
__global__ void finish_kernel(const float* __restrict__ cb,
                              float* __restrict__ out) {
    int bid = blockIdx.x, tid = threadIdx.x;
    if (bid < 16384) {                    // zq: 4194304 float4s
        int i = bid * 256 + tid;
        int t = i >> 6, cq = i & 63;
        int idx = g_idx[t];
        ((float4*)out)[i] = ((const float4*)(cb + idx * kC))[cq];
        return;
    }
    if (bid < 16640) {                    // idx casts
        int t = (bid - 16384) * 256 + tid;
        out[kOffIdxG + t] = (float)g_idx[kNTok + t];
        out[kOffIdxZ + t] = (float)g_idx[t];
        return;
    }
    {                                     // cosine: 2048 blocks
        int bw = bid - 16640;
        int b = bw >> 5, w = bw & 31;
        int c = tid;
        __shared__ int sig[32], siz[32];
        if (tid < 32) {
            int h = tid;
            int t = b * 1024 + h * 32 + w;
            sig[h] = g_idx[kNTok + t];
            siz[h] = g_idx[t];
        }
        __syncthreads();
        float num = 0.f, ng = 0.f, nz = 0.f;
        for (int h = 0; h < 32; ++h) {
            float g = cb[sig[h] * kC + c];
            float q = cb[siz[h] * kC + c];
            num = fmaf(g, q, num);
            ng  = fmaf(g, g, ng);
            nz  = fmaf(q, q, nz);
        }
        float den = fmaxf(sqrtf(ng), 1e-8f) * fmaxf(sqrtf(nz), 1e-8f);
        out[kOffCos + bw * kC + c] = num / den;
    }
}

// ---------------------------------------------------------------------------
extern "C" void kernel_launch(void* const* d_in, const int* in_sizes, int n_in,
                              void* d_out, int out_size) {
    const float* z  = (const float*)d_in[0];
    const float* gt = (const float*)d_in[1];
    const float* cb = (const float*)d_in[2];
    float* out = (float*)d_out;
    (void)in_sizes; (void)n_in; (void)out_size;

    cudaFuncSetAttribute(argmin_mma_kernel,
                         cudaFuncAttributeMaxDynamicSharedMemorySize, SMEM_BYTES);

    prep_all_kernel<<<33792, 256>>>(cb, z, gt);                  // launch 1
    argmin_mma_kernel<<<1024, 256, SMEM_BYTES>>>();              // launch 2
    refine_kernel<<<2048, 256>>>(z, gt, cb);                     // launch 3
    refine_commit_kernel<<<kFlagCap / 256, 256>>>();             // launch 4
    finish_kernel<<<18688, 256>>>(cb, out);                      // launch 5
}